// round 2
// baseline (speedup 1.0000x reference)
#include <cuda_runtime.h>

namespace {
constexpr int B = 8;
constexpr int N = 1024;
constexpr int C = 128;
constexpr float SCALEF = 20.0f;
constexpr float EPSF = 1e-12f;
constexpr float LOG2E = 1.4426950408889634f;
constexpr float K2 = 4.808983469629878f;   // log2(e)/0.3
constexpr int SNB = 16;                    // sinkhorn blocks per batch
}

__device__ float g_Fn[2 * B * N * C];
__device__ float g_via[B * N * C];
__device__ float g_scrA[(size_t)B * N * N];
__device__ float g_scrB[(size_t)B * N * N];
__device__ float g_r[B * N];
__device__ float g_c[B * N];
__device__ float g_maxA[B * N], g_sumA[B * N];
__device__ float g_maxB[B * N], g_sumB[B * N];
__device__ unsigned g_bar[B];
__device__ int g_correct;
__device__ float g_pL[B * N], g_pC[B * N], g_pP[B * N];

__device__ __forceinline__ float fex2(float x) {
    float y; asm("ex2.approx.ftz.f32 %0, %1;" : "=f"(y) : "f"(x)); return y;
}
__device__ __forceinline__ float flg2(float x) {
    float y; asm("lg2.approx.ftz.f32 %0, %1;" : "=f"(y) : "f"(x)); return y;
}

// ---------------------------------------------------------------------------
__global__ void k_init() {
    int i = blockIdx.x * blockDim.x + threadIdx.x;
    if (i < B * N) { g_r[i] = 0.f; g_c[i] = 0.f; }
    if (i < B) g_bar[i] = 0u;
    if (i == 0) g_correct = 0;
}

// one block (128 threads) per feature row
__global__ void __launch_bounds__(128) k_norm(const float* __restrict__ feats) {
    int row = blockIdx.x;
    const float* p = feats + (size_t)row * C;
    float v = p[threadIdx.x];
    float s = v * v;
    #pragma unroll
    for (int o = 16; o; o >>= 1) s += __shfl_xor_sync(0xffffffffu, s, o);
    __shared__ float sh[4];
    if ((threadIdx.x & 31) == 0) sh[threadIdx.x >> 5] = s;
    __syncthreads();
    s = sh[0] + sh[1] + sh[2] + sh[3];
    float scl = SCALEF / fmaxf(sqrtf(s), EPSF);
    g_Fn[(size_t)row * C + threadIdx.x] = v * scl;
}

// ---------------------------------------------------------------------------
// NT gemm: C[n][m] = sum_k A[n][k]*Bm[m][k], K=128. 128x128 tile, per-thread 8x8.
__global__ void __launch_bounds__(256) k_gemm_nt(int mode) {
    int b = blockIdx.z;
    const float* Ag; const float* Bg; float* Cg;
    if (mode == 0) {
        Ag = g_Fn + (size_t)(2 * b) * N * C;
        Bg = g_Fn + (size_t)(2 * ((b + 1) & 7)) * N * C;
        Cg = g_scrA + (size_t)b * N * N;
    } else if (mode == 1) {
        Ag = g_via + (size_t)b * N * C;
        Bg = g_Fn + (size_t)(2 * b + 1) * N * C;
        Cg = g_scrA + (size_t)b * N * N;
    } else {
        Ag = g_Fn + (size_t)(2 * b) * N * C;
        Bg = g_Fn + (size_t)(2 * b + 1) * N * C;
        Cg = g_scrB + (size_t)b * N * N;
    }
    int m0 = blockIdx.x * 128, n0 = blockIdx.y * 128;
    __shared__ float As[32 * 132];
    __shared__ float Bs[32 * 132];
    int tid = threadIdx.x;
    int tx = tid & 15, ty = tid >> 4;

    float acc[2][2][4][4] = {};

    for (int kc = 0; kc < 4; kc++) {
        int kb = kc * 32;
        if (kc) __syncthreads();
        #pragma unroll
        for (int t = 0; t < 4; t++) {
            int lin = tid + 256 * t;
            int k = lin & 31, rg = lin >> 5;
            const float* pA = Ag + (size_t)(n0 + rg * 4) * C + kb + k;
            float4 va = make_float4(pA[0], pA[C], pA[2 * C], pA[3 * C]);
            *reinterpret_cast<float4*>(&As[k * 132 + rg * 4]) = va;
            const float* pB = Bg + (size_t)(m0 + rg * 4) * C + kb + k;
            float4 vb = make_float4(pB[0], pB[C], pB[2 * C], pB[3 * C]);
            *reinterpret_cast<float4*>(&Bs[k * 132 + rg * 4]) = vb;
        }
        __syncthreads();
        #pragma unroll 8
        for (int k = 0; k < 32; k++) {
            float4 a0 = *reinterpret_cast<const float4*>(&As[k * 132 + 4 * ty]);
            float4 a1 = *reinterpret_cast<const float4*>(&As[k * 132 + 64 + 4 * ty]);
            float4 b0 = *reinterpret_cast<const float4*>(&Bs[k * 132 + 4 * tx]);
            float4 b1 = *reinterpret_cast<const float4*>(&Bs[k * 132 + 64 + 4 * tx]);
            float ar[2][4] = {{a0.x, a0.y, a0.z, a0.w}, {a1.x, a1.y, a1.z, a1.w}};
            float br[2][4] = {{b0.x, b0.y, b0.z, b0.w}, {b1.x, b1.y, b1.z, b1.w}};
            #pragma unroll
            for (int ri = 0; ri < 2; ri++)
                #pragma unroll
                for (int i = 0; i < 4; i++) {
                    float av = ar[ri][i];
                    #pragma unroll
                    for (int ci = 0; ci < 2; ci++)
                        #pragma unroll
                        for (int j = 0; j < 4; j++)
                            acc[ri][ci][i][j] += av * br[ci][j];
                }
        }
    }

    #pragma unroll
    for (int ri = 0; ri < 2; ri++)
        #pragma unroll
        for (int i = 0; i < 4; i++) {
            int row = n0 + ri * 64 + 4 * ty + i;
            #pragma unroll
            for (int ci = 0; ci < 2; ci++) {
                int col = m0 + ci * 64 + 4 * tx;
                float4 w = make_float4(acc[ri][ci][i][0], acc[ri][ci][i][1],
                                       acc[ri][ci][i][2], acc[ri][ci][i][3]);
                *reinterpret_cast<float4*>(&Cg[(size_t)row * N + col]) = w;
            }
        }
}

// ---------------------------------------------------------------------------
// in-place row softmax of g_scrA (8192 rows x 1024)
__global__ void __launch_bounds__(256) k_rowsoftmax() {
    size_t row = blockIdx.x;
    float* p = g_scrA + row * N;
    int tid = threadIdx.x;
    float v[4];
    float mx = -1e30f;
    #pragma unroll
    for (int i = 0; i < 4; i++) { v[i] = p[tid + 256 * i]; mx = fmaxf(mx, v[i]); }
    #pragma unroll
    for (int o = 16; o; o >>= 1) mx = fmaxf(mx, __shfl_xor_sync(0xffffffffu, mx, o));
    __shared__ float shm[8], shs[8];
    if ((tid & 31) == 0) shm[tid >> 5] = mx;
    __syncthreads();
    mx = fmaxf(fmaxf(fmaxf(shm[0], shm[1]), fmaxf(shm[2], shm[3])),
               fmaxf(fmaxf(shm[4], shm[5]), fmaxf(shm[6], shm[7])));
    float s = 0.f;
    #pragma unroll
    for (int i = 0; i < 4; i++) { v[i] = fex2((v[i] - mx) * LOG2E); s += v[i]; }
    #pragma unroll
    for (int o = 16; o; o >>= 1) s += __shfl_xor_sync(0xffffffffu, s, o);
    if ((tid & 31) == 0) shs[tid >> 5] = s;
    __syncthreads();
    s = shs[0] + shs[1] + shs[2] + shs[3] + shs[4] + shs[5] + shs[6] + shs[7];
    float inv = 1.0f / s;
    #pragma unroll
    for (int i = 0; i < 4; i++) p[tid + 256 * i] = v[i] * inv;
}

// ---------------------------------------------------------------------------
// NN gemm: via[b] = smcorr_1a[b] (1024x1024) @ fa[b] (1024x128). 64x128 tile.
__global__ void __launch_bounds__(256) k_gemm_nn() {
    int b = blockIdx.y;
    int n0 = blockIdx.x * 64;
    const float* P = g_scrA + (size_t)b * N * N;
    const float* V = g_Fn + (size_t)(2 * ((b + 1) & 7)) * N * C;
    float* O = g_via + (size_t)b * N * C;
    __shared__ float As[32 * 68];
    __shared__ float Bs[32 * 132];
    int tid = threadIdx.x, tx = tid & 15, ty = tid >> 4;
    float acc[2][4][4] = {};
    for (int kc = 0; kc < 32; kc++) {
        int kb = kc * 32;
        if (kc) __syncthreads();
        #pragma unroll
        for (int t = 0; t < 2; t++) {
            int lin = tid + 256 * t;
            int k = lin & 31, rg = lin >> 5;
            const float* pA = P + (size_t)(n0 + rg * 4) * N + kb + k;
            float4 va = make_float4(pA[0], pA[N], pA[2 * N], pA[3 * N]);
            *reinterpret_cast<float4*>(&As[k * 68 + rg * 4]) = va;
        }
        #pragma unroll
        for (int t = 0; t < 4; t++) {
            int lin = tid + 256 * t;
            int kr = lin >> 5, c4 = lin & 31;
            float4 vb = *reinterpret_cast<const float4*>(&V[(size_t)(kb + kr) * C + c4 * 4]);
            *reinterpret_cast<float4*>(&Bs[kr * 132 + c4 * 4]) = vb;
        }
        __syncthreads();
        #pragma unroll 8
        for (int k = 0; k < 32; k++) {
            float4 a  = *reinterpret_cast<const float4*>(&As[k * 68 + 4 * ty]);
            float4 b0 = *reinterpret_cast<const float4*>(&Bs[k * 132 + 4 * tx]);
            float4 b1 = *reinterpret_cast<const float4*>(&Bs[k * 132 + 64 + 4 * tx]);
            float ar[4] = {a.x, a.y, a.z, a.w};
            float br[2][4] = {{b0.x, b0.y, b0.z, b0.w}, {b1.x, b1.y, b1.z, b1.w}};
            #pragma unroll
            for (int i = 0; i < 4; i++) {
                float av = ar[i];
                #pragma unroll
                for (int ci = 0; ci < 2; ci++)
                    #pragma unroll
                    for (int j = 0; j < 4; j++)
                        acc[ci][i][j] += av * br[ci][j];
            }
        }
    }
    #pragma unroll
    for (int i = 0; i < 4; i++) {
        int row = n0 + 4 * ty + i;
        #pragma unroll
        for (int ci = 0; ci < 2; ci++) {
            int col = ci * 64 + 4 * tx;
            float4 w = make_float4(acc[ci][i][0], acc[ci][i][1],
                                   acc[ci][i][2], acc[ci][i][3]);
            *reinterpret_cast<float4*>(&O[(size_t)row * C + col]) = w;
        }
    }
}

// ---------------------------------------------------------------------------
// row stats: which=0 -> scrA (+ argmax==n count), which=1 -> scrB
__global__ void __launch_bounds__(256) k_rowstats() {
    size_t row = blockIdx.x;
    int which = blockIdx.y;
    const float* p = (which ? g_scrB : g_scrA) + row * N;
    int tid = threadIdx.x;
    float v[4];
    float mx = -1e30f; int arg = 0;
    #pragma unroll
    for (int i = 0; i < 4; i++) {
        v[i] = p[tid + 256 * i];
        if (v[i] > mx) { mx = v[i]; arg = tid + 256 * i; }
    }
    #pragma unroll
    for (int o = 16; o; o >>= 1) {
        float om = __shfl_xor_sync(0xffffffffu, mx, o);
        int oa = __shfl_xor_sync(0xffffffffu, arg, o);
        if (om > mx || (om == mx && oa < arg)) { mx = om; arg = oa; }
    }
    __shared__ float shm[8]; __shared__ int sha[8]; __shared__ float shs[8];
    if ((tid & 31) == 0) { shm[tid >> 5] = mx; sha[tid >> 5] = arg; }
    __syncthreads();
    float bm = shm[0]; int ba = sha[0];
    #pragma unroll
    for (int q = 1; q < 8; q++)
        if (shm[q] > bm || (shm[q] == bm && sha[q] < ba)) { bm = shm[q]; ba = sha[q]; }
    float s = 0.f;
    #pragma unroll
    for (int i = 0; i < 4; i++) s += fex2((v[i] - bm) * LOG2E);
    #pragma unroll
    for (int o = 16; o; o >>= 1) s += __shfl_xor_sync(0xffffffffu, s, o);
    if ((tid & 31) == 0) shs[tid >> 5] = s;
    __syncthreads();
    if (tid == 0) {
        float st = shs[0] + shs[1] + shs[2] + shs[3] + shs[4] + shs[5] + shs[6] + shs[7];
        if (which == 0) {
            g_maxA[row] = bm; g_sumA[row] = st;
            if (ba == (int)(row & 1023)) atomicAdd(&g_correct, 1);
        } else {
            g_maxB[row] = bm; g_sumB[row] = st;
        }
    }
}

// ---------------------------------------------------------------------------
__device__ __forceinline__ void batch_bar(int b, unsigned target) {
    __syncthreads();
    if (threadIdx.x == 0) {
        __threadfence();
        atomicAdd(&g_bar[b], 1u);
        volatile unsigned* vb = (volatile unsigned*)&g_bar[b];
        while (*vb < target) { }
        __threadfence();
    }
    __syncthreads();
}

// persistent sinkhorn: 16 blocks/batch, rank-1 (r,c) updates in log2 domain
__global__ void __launch_bounds__(256) k_sinkhorn() {
    int b = blockIdx.x >> 4, sub = blockIdx.x & 15;
    const float* M = g_scrA + (size_t)b * N * N;
    __shared__ float sv[1024];
    __shared__ float cm[4][64];
    __shared__ float cs[4][64];
    int tid = threadIdx.x;
    int warp = tid >> 5, lane = tid & 31;
    int tc = tid & 63, tj = tid >> 6;
    unsigned bar_t = 0;

    for (int it = 0; it < 30; it++) {
        // row phase: r[n] = -lse2_m(M[n][m]*K2 + c[m])
        for (int i = tid; i < N; i += 256) sv[i] = g_c[b * N + i];
        __syncthreads();
        for (int rr = 0; rr < 8; rr++) {
            int n = sub * 64 + warp * 8 + rr;
            const float* rowp = M + (size_t)n * N;
            float vals[32];
            float mx = -1e30f;
            #pragma unroll
            for (int j = 0; j < 32; j++) {
                float x = rowp[lane + 32 * j] * K2 + sv[lane + 32 * j];
                vals[j] = x;
                mx = fmaxf(mx, x);
            }
            #pragma unroll
            for (int o = 16; o; o >>= 1) mx = fmaxf(mx, __shfl_xor_sync(0xffffffffu, mx, o));
            float s = 0.f;
            #pragma unroll
            for (int j = 0; j < 32; j++) s += fex2(vals[j] - mx);
            #pragma unroll
            for (int o = 16; o; o >>= 1) s += __shfl_xor_sync(0xffffffffu, s, o);
            if (lane == 0) g_r[b * N + n] = -(mx + flg2(s));
        }
        bar_t += SNB; batch_bar(b, bar_t);

        // col phase: c[m] = -lse2_n(M[n][m]*K2 + r[n])
        for (int i = tid; i < N; i += 256) sv[i] = g_r[b * N + i];
        __syncthreads();
        {
            int m = sub * 64 + tc;
            float mx = -1e30f, s = 0.f;
            for (int n = tj; n < N; n += 4) {
                float x = M[(size_t)n * N + m] * K2 + sv[n];
                if (x <= mx) {
                    s += fex2(x - mx);
                } else {
                    s = s * fex2(mx - x) + 1.0f;
                    mx = x;
                }
            }
            cm[tj][tc] = mx; cs[tj][tc] = s;
            __syncthreads();
            if (tj == 0) {
                float M0 = cm[0][tc], S0 = cs[0][tc];
                #pragma unroll
                for (int q = 1; q < 4; q++) {
                    float Mq = cm[q][tc], Sq = cs[q][tc];
                    float nm = fmaxf(M0, Mq);
                    S0 = S0 * fex2(M0 - nm) + Sq * fex2(Mq - nm);
                    M0 = nm;
                }
                g_c[b * N + m] = -(M0 + flg2(S0));
            }
            __syncthreads();
        }
        bar_t += SNB; batch_bar(b, bar_t);
    }
}

// ---------------------------------------------------------------------------
// fused final pass: dist, both softmaxes, sink; per-row partial reductions
__global__ void __launch_bounds__(256) k_final(const float* __restrict__ pc0) {
    int rowi = blockIdx.x;
    int b = rowi >> 10, n = rowi & 1023;
    size_t row = rowi;
    const float* pA = g_scrA + row * N;
    const float* pB = g_scrB + row * N;
    float mA = g_maxA[row], iA = 1.0f / g_sumA[row];
    float mB = g_maxB[row], iB = 1.0f / g_sumB[row];
    float rn = g_r[row];
    const float* pc = pc0 + (size_t)b * N * 3;
    const float* cvec = g_c + b * N;
    int tid = threadIdx.x;

    __shared__ float spc[3 * 1024];
    __shared__ float scv[1024];
    for (int i = tid; i < 3 * 1024; i += 256) spc[i] = pc[i];
    for (int i = tid; i < 1024; i += 256) scv[i] = cvec[i];
    __syncthreads();

    float px = spc[3 * n], py = spc[3 * n + 1], pz = spc[3 * n + 2];
    float aL = 0.f, aC = 0.f, aP = 0.f;
    #pragma unroll
    for (int t = 0; t < 4; t++) {
        int m = tid + 256 * t;
        float xA = pA[m], xB = pB[m];
        float smA = fex2((xA - mA) * LOG2E) * iA;
        float smB = fex2((xB - mB) * LOG2E) * iB;
        float dx = px - spc[3 * m], dy = py - spc[3 * m + 1], dz = pz - spc[3 * m + 2];
        float d2 = dx * dx + dy * dy + dz * dz;
        float dist = sqrtf(sqrtf(d2));
        aL += dist * (smA + smB);
        float sink = fex2(xA * K2 + rn + scv[m]);
        aC += fabsf(sink - smA);
        aP += (m == n) ? fabsf(1.0f - sink) : sink;
    }
    #pragma unroll
    for (int o = 16; o; o >>= 1) {
        aL += __shfl_xor_sync(0xffffffffu, aL, o);
        aC += __shfl_xor_sync(0xffffffffu, aC, o);
        aP += __shfl_xor_sync(0xffffffffu, aP, o);
    }
    __shared__ float s1[8], s2[8], s3[8];
    if ((tid & 31) == 0) { s1[tid >> 5] = aL; s2[tid >> 5] = aC; s3[tid >> 5] = aP; }
    __syncthreads();
    if (tid == 0) {
        float tL = 0.f, tC = 0.f, tP = 0.f;
        #pragma unroll
        for (int q = 0; q < 8; q++) { tL += s1[q]; tC += s2[q]; tP += s3[q]; }
        g_pL[row] = tL; g_pC[row] = tC; g_pP[row] = tP;
    }
}

// ---------------------------------------------------------------------------
__global__ void __launch_bounds__(256) k_out(float* __restrict__ out) {
    int tid = threadIdx.x;
    float sL = 0.f, sC = 0.f, sP = 0.f;
    for (int i = tid; i < B * N; i += 256) {
        sL += g_pL[i]; sC += g_pC[i]; sP += g_pP[i];
    }
    #pragma unroll
    for (int o = 16; o; o >>= 1) {
        sL += __shfl_xor_sync(0xffffffffu, sL, o);
        sC += __shfl_xor_sync(0xffffffffu, sC, o);
        sP += __shfl_xor_sync(0xffffffffu, sP, o);
    }
    __shared__ float s1[8], s2[8], s3[8];
    if ((tid & 31) == 0) { s1[tid >> 5] = sL; s2[tid >> 5] = sC; s3[tid >> 5] = sP; }
    __syncthreads();
    if (tid == 0) {
        float tL = 0.f, tC = 0.f, tP = 0.f;
        #pragma unroll
        for (int q = 0; q < 8; q++) { tL += s1[q]; tC += s2[q]; tP += s3[q]; }
        float invN = 1.0f / (float)N;
        float loss = tL * invN;
        float Lc = 3.0f * tC * invN;
        float perm = 3.0f * tP * invN;
        float corr = (float)g_correct;
        float invB = 1.0f / (float)B;
        out[0] = (loss + Lc) * invB;
        out[1] = loss * invB;
        out[2] = Lc * invB;
        out[3] = corr * invB;
        out[4] = perm * invB;
    }
}

// ---------------------------------------------------------------------------
extern "C" void kernel_launch(void* const* d_in, const int* in_sizes, int n_in,
                              void* d_out, int out_size) {
    const float* feats = (const float*)d_in[0];
    const float* pc0 = (const float*)d_in[1];
    float* out = (float*)d_out;

    k_init<<<32, 256>>>();
    k_norm<<<2 * B * N, 128>>>(feats);
    k_gemm_nt<<<dim3(8, 8, 8), 256>>>(0);          // corr_1a -> scrA
    k_rowsoftmax<<<B * N, 256>>>();                // smcorr_1a in place
    k_gemm_nn<<<dim3(16, 8), 256>>>();             // via = smcorr_1a @ fa
    k_gemm_nt<<<dim3(8, 8, 8), 256>>>(1);          // corr_1a2 -> scrA
    k_gemm_nt<<<dim3(8, 8, 8), 256>>>(2);          // corr_12 -> scrB
    k_rowstats<<<dim3(B * N, 2), 256>>>();
    k_sinkhorn<<<B * SNB, 256>>>();
    k_final<<<B * N, 256>>>(pc0);
    k_out<<<1, 256>>>(out);
}